// round 4
// baseline (speedup 1.0000x reference)
#include <cuda_runtime.h>
#include <cuda_bf16.h>
#include <cstdint>
#include <math.h>

// LSTM cell B=4096, I=H=1024, fully fused:
//   convert_a: [x|h] -> bf16 hi/lo A[4096,2048]
//   convert_w: gate-interleaved transpose W'[n'][k], n' = hid*4+gate, bf16 hi/lo
//              (+ fused bias b'[n'] = bi+bh permuted)
//   lstm_gemm_mma: ifgo' = A @ W'^T via mma.sync bf16 hi/lo (3 MMAs),
//              3-stage cp.async pipeline, epilogue computes activations and
//              writes h_new/c_new DIRECTLY (no ifgo scratch, no act kernel).

#define BM 128
#define BN 128
#define BK 32
#define KTOT 2048
#define NITER (KTOT / BK)

// smem: padded rows, 32+8 halves = 80B pitch (conflict-free ldmatrix)
#define ROWB 80
#define TILE_B (128 * ROWB)            // 10240 B per tile
#define OFF_AHI 0
#define OFF_ALO (TILE_B)
#define OFF_BHI (2 * TILE_B)
#define OFF_BLO (3 * TILE_B)
#define STAGE   (4 * TILE_B)           // 40960 B
#define NSTAGE  3
#define SMEM_TOTAL (NSTAGE * STAGE)    // 122880 B

// ---- scratch (allocation-free rule: __device__ globals) ----
__device__ __nv_bfloat16 g_Ahi[4096ull * 2048], g_Alo[4096ull * 2048];
__device__ __nv_bfloat16 g_Whi[4096ull * 2048], g_Wlo[4096ull * 2048];  // [n'][k]
__device__ float g_bias[4096];                                          // permuted bi+bh

__device__ __forceinline__ uint32_t smem_u32(const void* p) {
    uint32_t a;
    asm("{ .reg .u64 t; cvta.to.shared.u64 t, %1; cvt.u32.u64 %0, t; }" : "=r"(a) : "l"(p));
    return a;
}
__device__ __forceinline__ void cp_async16(uint32_t s, const void* g) {
    asm volatile("cp.async.cg.shared.global [%0], [%1], 16;\n" :: "r"(s), "l"(g));
}
#define CP_COMMIT() asm volatile("cp.async.commit_group;\n" ::: "memory")
#define CP_WAIT(n)  asm volatile("cp.async.wait_group %0;\n" :: "n"(n) : "memory")

__device__ __forceinline__ void ldsm_x4(uint32_t* r, uint32_t addr) {
    asm volatile("ldmatrix.sync.aligned.m8n8.x4.shared.b16 {%0,%1,%2,%3}, [%4];"
                 : "=r"(r[0]), "=r"(r[1]), "=r"(r[2]), "=r"(r[3]) : "r"(addr));
}
__device__ __forceinline__ void mma_bf16(float* c, const uint32_t* a, const uint32_t* b) {
    asm volatile("mma.sync.aligned.m16n8k16.row.col.f32.bf16.bf16.f32 "
                 "{%0,%1,%2,%3}, {%4,%5,%6,%7}, {%8,%9}, {%0,%1,%2,%3};"
                 : "+f"(c[0]), "+f"(c[1]), "+f"(c[2]), "+f"(c[3])
                 : "r"(a[0]), "r"(a[1]), "r"(a[2]), "r"(a[3]), "r"(b[0]), "r"(b[1]));
}

__device__ __forceinline__ float sigmoidf_fast(float v) {
    return 1.f / (1.f + __expf(-v));
}
__device__ __forceinline__ float tanhf_fast(float v) {
    return 2.f / (1.f + __expf(-2.f * v)) - 1.f;
}

// ============================================================
// pre-kernel 1: A = [x|h] -> bf16 hi/lo, row-major [4096, 2048]
// ============================================================
__global__ __launch_bounds__(256)
void convert_a(const float* __restrict__ x, const float* __restrict__ h)
{
    const int idx = blockIdx.x * 256 + threadIdx.x;   // over 4096*512 float4
    const int m = idx >> 9;
    const int kq = idx & 511;
    float4 v = (kq < 256)
        ? reinterpret_cast<const float4*>(x)[(size_t)m * 256 + kq]
        : reinterpret_cast<const float4*>(h)[(size_t)m * 256 + (kq - 256)];
    __nv_bfloat16 h0 = __float2bfloat16(v.x), h1 = __float2bfloat16(v.y);
    __nv_bfloat16 h2 = __float2bfloat16(v.z), h3 = __float2bfloat16(v.w);
    __nv_bfloat16 l0 = __float2bfloat16(v.x - __bfloat162float(h0));
    __nv_bfloat16 l1 = __float2bfloat16(v.y - __bfloat162float(h1));
    __nv_bfloat16 l2 = __float2bfloat16(v.z - __bfloat162float(h2));
    __nv_bfloat16 l3 = __float2bfloat16(v.w - __bfloat162float(h3));
    __nv_bfloat162 hp0(h0, h1), hp1(h2, h3), lp0(l0, l1), lp1(l2, l3);
    uint2 hv, lv;
    hv.x = *reinterpret_cast<uint32_t*>(&hp0); hv.y = *reinterpret_cast<uint32_t*>(&hp1);
    lv.x = *reinterpret_cast<uint32_t*>(&lp0); lv.y = *reinterpret_cast<uint32_t*>(&lp1);
    reinterpret_cast<uint2*>(g_Ahi)[idx] = hv;
    reinterpret_cast<uint2*>(g_Alo)[idx] = lv;
}

// ============================================================
// pre-kernel 2: gate-interleaved transposed weights.
// Output row n' = hid*4 + gate; source col n = gate*1024 + hid.
// Also writes g_bias[n'] = bi[n] + bh[n].
// ============================================================
__global__ __launch_bounds__(256)
void convert_w(const float* __restrict__ wi, const float* __restrict__ wh,
               const float* __restrict__ bi, const float* __restrict__ bh)
{
    __shared__ float tile[32][33];
    const int k0 = blockIdx.x * 32;
    const int n0 = blockIdx.y * 32;     // block of 32 consecutive n' (8 hids x 4 gates)
    const int tx = threadIdx.x, ty = threadIdx.y;   // (32, 8)

    // source col for this thread's read lane: g = tx>>3, hid_off = tx&7
    const int g_gate = tx >> 3;
    const int hid = (n0 >> 2) + (tx & 7);
    const int n_src = g_gate * 1024 + hid;
    // within-block n' offset for that source col:
    const int cp = ((tx & 7) << 2) | g_gate;

    #pragma unroll
    for (int j = 0; j < 4; j++) {
        int k = k0 + ty + j * 8;
        const float* w = (k < 1024) ? (wi + (size_t)k * 4096) : (wh + (size_t)(k - 1024) * 4096);
        tile[ty + j * 8][cp] = w[n_src];
    }
    if (blockIdx.x == 0 && ty == 0)
        g_bias[n0 + cp] = bi[n_src] + bh[n_src];
    __syncthreads();

    #pragma unroll
    for (int j = 0; j < 4; j++) {
        int np = n0 + ty + j * 8;       // output row n'
        float v = tile[tx][ty + j * 8];
        __nv_bfloat16 hi = __float2bfloat16(v);
        __nv_bfloat16 lo = __float2bfloat16(v - __bfloat162float(hi));
        g_Whi[(size_t)np * 2048 + k0 + tx] = hi;
        g_Wlo[(size_t)np * 2048 + k0 + tx] = lo;
    }
}

// ============================================================
// GEMM + fused LSTM epilogue.
// 128x128x32 CTA tile, 8 warps (4m x 2n), warp 32x64, 3-stage cp.async.
// ============================================================
__global__ __launch_bounds__(256)
void lstm_gemm_mma(const float* __restrict__ c_t, float* __restrict__ out)
{
    extern __shared__ char smem[];
    const uint32_t sb = smem_u32(smem);
    const int tid = threadIdx.x;
    const int lane = tid & 31;
    const int w = tid >> 5;
    const int wm0 = (w & 3) * 32;       // warp m offset in tile
    const int wn0 = (w >> 2) * 64;      // warp n offset in tile
    const int bm = blockIdx.y * BM;
    const int bn = blockIdx.x * BN;

    float acc[2][8][4];
    #pragma unroll
    for (int i = 0; i < 2; i++)
        #pragma unroll
        for (int j = 0; j < 8; j++)
            #pragma unroll
            for (int q = 0; q < 4; q++) acc[i][j][q] = 0.f;

    auto load_stage = [&](int c, int buf) {
        const int kk = c * BK;
        const uint32_t st = sb + buf * STAGE;
        #pragma unroll
        for (int t = 0; t < 2; t++) {
            int idx = tid + t * 256;     // 0..511
            int row = idx >> 2;          // 0..127
            int c16 = idx & 3;           // 16B chunk in row
            uint32_t so = (uint32_t)(row * ROWB + c16 * 16);
            size_t ga = (size_t)(bm + row) * KTOT + kk + c16 * 8;
            size_t gb = (size_t)(bn + row) * KTOT + kk + c16 * 8;
            cp_async16(st + OFF_AHI + so, g_Ahi + ga);
            cp_async16(st + OFF_ALO + so, g_Alo + ga);
            cp_async16(st + OFF_BHI + so, g_Whi + gb);
            cp_async16(st + OFF_BLO + so, g_Wlo + gb);
        }
        CP_COMMIT();
    };

    load_stage(0, 0);
    load_stage(1, 1);

    for (int c = 0; c < NITER; c++) {
        const int buf = c % NSTAGE;
        if (c + 2 < NITER) {
            load_stage(c + 2, (c + 2) % NSTAGE);
            CP_WAIT(2);
        } else if (c + 1 < NITER) {
            CP_WAIT(1);
        } else {
            CP_WAIT(0);
        }
        __syncthreads();

        const uint32_t st = sb + buf * STAGE;
        #pragma unroll
        for (int ks = 0; ks < 2; ks++) {
            uint32_t ah[2][4], al[2][4];
            #pragma unroll
            for (int tm = 0; tm < 2; tm++) {
                uint32_t ra = (uint32_t)((wm0 + tm * 16 + (lane & 15)) * ROWB
                                         + ks * 32 + ((lane >> 4) << 4));
                ldsm_x4(ah[tm], st + OFF_AHI + ra);
                ldsm_x4(al[tm], st + OFF_ALO + ra);
            }
            #pragma unroll
            for (int tn4 = 0; tn4 < 4; tn4++) {
                uint32_t rb = (uint32_t)((wn0 + tn4 * 16 + ((lane >> 4) << 3) + (lane & 7)) * ROWB
                                         + ks * 32 + (((lane >> 3) & 1) << 4));
                uint32_t bh[4], bl[4];
                ldsm_x4(bh, st + OFF_BHI + rb);
                ldsm_x4(bl, st + OFF_BLO + rb);
                #pragma unroll
                for (int tm = 0; tm < 2; tm++) {
                    #pragma unroll
                    for (int s = 0; s < 2; s++) {
                        float* cc = acc[tm][tn4 * 2 + s];
                        mma_bf16(cc, ah[tm], &bh[2 * s]);   // hi*hi
                        mma_bf16(cc, ah[tm], &bl[2 * s]);   // hi*lo
                        mma_bf16(cc, al[tm], &bh[2 * s]);   // lo*hi
                    }
                }
            }
        }
        __syncthreads();
    }

    // ---- fused LSTM epilogue ----
    // Columns n' = hid*4 + gate. Thread cols: col0+2*tq, col0+2*tq+1.
    //   tq even -> (i,f) of hid; tq odd -> (g,o) of same hid (pair via shfl_xor 1).
    //   Even lane computes row quad; odd lane computes row quad+8.
    const int quad = lane >> 2;
    const int tq = lane & 3;
    const bool evenq = (tq & 1) == 0;

    #pragma unroll
    for (int tm = 0; tm < 2; tm++) {
        const int m_r = bm + wm0 + tm * 16 + quad + (evenq ? 0 : 8);
        #pragma unroll
        for (int tn = 0; tn < 8; tn++) {
            const int col0 = bn + wn0 + tn * 8;     // multiple of 8
            const float2 bv = *reinterpret_cast<const float2*>(&g_bias[col0 + 2 * tq]);
            float c0 = acc[tm][tn][0] + bv.x;
            float c1 = acc[tm][tn][1] + bv.y;
            float c2 = acc[tm][tn][2] + bv.x;
            float c3 = acc[tm][tn][3] + bv.y;
            float p0 = __shfl_xor_sync(0xffffffffu, c0, 1);
            float p1 = __shfl_xor_sync(0xffffffffu, c1, 1);
            float p2 = __shfl_xor_sync(0xffffffffu, c2, 1);
            float p3 = __shfl_xor_sync(0xffffffffu, c3, 1);
            float gi, gf, gg, go;
            if (evenq) { gi = c0; gf = c1; gg = p0; go = p1; }   // row quad
            else       { gi = p2; gf = p3; gg = c2; go = c3; }   // row quad+8
            const int hid = (col0 >> 2) + (tq >> 1);
            const float ctv = c_t[(size_t)m_r * 1024 + hid];
            const float si = sigmoidf_fast(gi);
            const float sf = sigmoidf_fast(gf);
            const float so = sigmoidf_fast(go);
            const float tg = tanhf_fast(gg);
            const float cn = sf * ctv + si * tg;
            const float hn = so * tanhf_fast(cn);
            out[(size_t)m_r * 1024 + hid] = hn;
            out[4096ull * 1024 + (size_t)m_r * 1024 + hid] = cn;
        }
    }
}

// ============================================================
extern "C" void kernel_launch(void* const* d_in, const int* in_sizes, int n_in,
                              void* d_out, int out_size)
{
    (void)in_sizes; (void)n_in; (void)out_size;
    const float* x  = (const float*)d_in[0];
    const float* ht = (const float*)d_in[1];
    const float* ct = (const float*)d_in[2];
    const float* wi = (const float*)d_in[3];
    const float* wh = (const float*)d_in[4];
    const float* bi = (const float*)d_in[5];
    const float* bh = (const float*)d_in[6];
    float* out = (float*)d_out;

    cudaFuncSetAttribute(lstm_gemm_mma, cudaFuncAttributeMaxDynamicSharedMemorySize, SMEM_TOTAL);

    convert_a<<<4096 * 512 / 256, 256>>>(x, ht);
    convert_w<<<dim3(2048 / 32, 4096 / 32), dim3(32, 8)>>>(wi, wh, bi, bh);
    lstm_gemm_mma<<<dim3(4096 / BN, 4096 / BM), 256, SMEM_TOTAL>>>(ct, out);
}

// round 5
// speedup vs baseline: 1.2386x; 1.2386x over previous
#include <cuda_runtime.h>
#include <cuda_bf16.h>
#include <cstdint>
#include <math.h>

// LSTM cell B=4096, I=H=1024, fused:
//   convert_a: [x|h] -> bf16 hi/lo A[4096,2048]
//   convert_w: gate-interleaved transpose W'[n'][k], n' = hid*4+gate, bf16 hi/lo (+ bias)
//   lstm_gemm_mma: A @ W'^T via mma.sync bf16 hi/lo (3 MMAs), 2-stage cp.async,
//     2 CTAs/SM, epilogue: smem-staged coalesced c_t load + h/c stores.

#define BM 128
#define BN 128
#define BK 32
#define KTOT 2048
#define NITER (KTOT / BK)

#define ROWB 80
#define TILE_B (128 * ROWB)            // 10240 B per tile
#define OFF_AHI 0
#define OFF_ALO (TILE_B)
#define OFF_BHI (2 * TILE_B)
#define OFF_BLO (3 * TILE_B)
#define STAGE   (4 * TILE_B)           // 40960 B
#define CT_OFF  (2 * STAGE)            // c_t staging tile, 128x36 floats
#define EPI_PITCH 36
#define H_OFF   0                      // overlays stage 0 after mainloop
#define C_OFF   (128 * EPI_PITCH * 4)  // 18432
#define SMEM_TOTAL (2 * STAGE + 128 * EPI_PITCH * 4)   // 100352 B

// ---- scratch (allocation-free rule: __device__ globals) ----
__device__ __nv_bfloat16 g_Ahi[4096ull * 2048], g_Alo[4096ull * 2048];
__device__ __nv_bfloat16 g_Whi[4096ull * 2048], g_Wlo[4096ull * 2048];  // [n'][k]
__device__ float g_bias[4096];                                          // permuted bi+bh

__device__ __forceinline__ uint32_t smem_u32(const void* p) {
    uint32_t a;
    asm("{ .reg .u64 t; cvta.to.shared.u64 t, %1; cvt.u32.u64 %0, t; }" : "=r"(a) : "l"(p));
    return a;
}
__device__ __forceinline__ void cp_async16(uint32_t s, const void* g) {
    asm volatile("cp.async.cg.shared.global [%0], [%1], 16;\n" :: "r"(s), "l"(g));
}
#define CP_COMMIT() asm volatile("cp.async.commit_group;\n" ::: "memory")
#define CP_WAIT(n)  asm volatile("cp.async.wait_group %0;\n" :: "n"(n) : "memory")

__device__ __forceinline__ void ldsm_x4(uint32_t* r, uint32_t addr) {
    asm volatile("ldmatrix.sync.aligned.m8n8.x4.shared.b16 {%0,%1,%2,%3}, [%4];"
                 : "=r"(r[0]), "=r"(r[1]), "=r"(r[2]), "=r"(r[3]) : "r"(addr));
}
__device__ __forceinline__ void mma_bf16(float* c, const uint32_t* a, const uint32_t* b) {
    asm volatile("mma.sync.aligned.m16n8k16.row.col.f32.bf16.bf16.f32 "
                 "{%0,%1,%2,%3}, {%4,%5,%6,%7}, {%8,%9}, {%0,%1,%2,%3};"
                 : "+f"(c[0]), "+f"(c[1]), "+f"(c[2]), "+f"(c[3])
                 : "r"(a[0]), "r"(a[1]), "r"(a[2]), "r"(a[3]), "r"(b[0]), "r"(b[1]));
}

__device__ __forceinline__ float sigmoidf_fast(float v) {
    return 1.f / (1.f + __expf(-v));
}
__device__ __forceinline__ float tanhf_fast(float v) {
    return 2.f / (1.f + __expf(-2.f * v)) - 1.f;
}

// ============================================================
__global__ __launch_bounds__(256)
void convert_a(const float* __restrict__ x, const float* __restrict__ h)
{
    const int idx = blockIdx.x * 256 + threadIdx.x;   // over 4096*512 float4
    const int m = idx >> 9;
    const int kq = idx & 511;
    float4 v = (kq < 256)
        ? reinterpret_cast<const float4*>(x)[(size_t)m * 256 + kq]
        : reinterpret_cast<const float4*>(h)[(size_t)m * 256 + (kq - 256)];
    __nv_bfloat16 h0 = __float2bfloat16(v.x), h1 = __float2bfloat16(v.y);
    __nv_bfloat16 h2 = __float2bfloat16(v.z), h3 = __float2bfloat16(v.w);
    __nv_bfloat16 l0 = __float2bfloat16(v.x - __bfloat162float(h0));
    __nv_bfloat16 l1 = __float2bfloat16(v.y - __bfloat162float(h1));
    __nv_bfloat16 l2 = __float2bfloat16(v.z - __bfloat162float(h2));
    __nv_bfloat16 l3 = __float2bfloat16(v.w - __bfloat162float(h3));
    __nv_bfloat162 hp0(h0, h1), hp1(h2, h3), lp0(l0, l1), lp1(l2, l3);
    uint2 hv, lv;
    hv.x = *reinterpret_cast<uint32_t*>(&hp0); hv.y = *reinterpret_cast<uint32_t*>(&hp1);
    lv.x = *reinterpret_cast<uint32_t*>(&lp0); lv.y = *reinterpret_cast<uint32_t*>(&lp1);
    reinterpret_cast<uint2*>(g_Ahi)[idx] = hv;
    reinterpret_cast<uint2*>(g_Alo)[idx] = lv;
}

// ============================================================
__global__ __launch_bounds__(256)
void convert_w(const float* __restrict__ wi, const float* __restrict__ wh,
               const float* __restrict__ bi, const float* __restrict__ bh)
{
    __shared__ float tile[32][33];
    const int k0 = blockIdx.x * 32;
    const int n0 = blockIdx.y * 32;     // 32 consecutive n' (8 hids x 4 gates)
    const int tx = threadIdx.x, ty = threadIdx.y;   // (32, 8)

    const int g_gate = tx >> 3;
    const int hid = (n0 >> 2) + (tx & 7);
    const int n_src = g_gate * 1024 + hid;
    const int cp = ((tx & 7) << 2) | g_gate;

    #pragma unroll
    for (int j = 0; j < 4; j++) {
        int k = k0 + ty + j * 8;
        const float* w = (k < 1024) ? (wi + (size_t)k * 4096) : (wh + (size_t)(k - 1024) * 4096);
        tile[ty + j * 8][cp] = w[n_src];
    }
    if (blockIdx.x == 0 && ty == 0)
        g_bias[n0 + cp] = bi[n_src] + bh[n_src];
    __syncthreads();

    #pragma unroll
    for (int j = 0; j < 4; j++) {
        int np = n0 + ty + j * 8;
        float v = tile[tx][ty + j * 8];
        __nv_bfloat16 hi = __float2bfloat16(v);
        __nv_bfloat16 lo = __float2bfloat16(v - __bfloat162float(hi));
        g_Whi[(size_t)np * 2048 + k0 + tx] = hi;
        g_Wlo[(size_t)np * 2048 + k0 + tx] = lo;
    }
}

// ============================================================
// GEMM + fused LSTM epilogue, 2-stage pipeline, 2 CTAs/SM.
// ============================================================
__global__ __launch_bounds__(256, 2)
void lstm_gemm_mma(const float* __restrict__ c_t, float* __restrict__ out)
{
    extern __shared__ char smem[];
    const uint32_t sb = smem_u32(smem);
    const int tid = threadIdx.x;
    const int lane = tid & 31;
    const int w = tid >> 5;
    const int wm0 = (w & 3) * 32;
    const int wn0 = (w >> 2) * 64;
    const int bm = blockIdx.y * BM;
    const int bn = blockIdx.x * BN;
    const int hid0 = bn >> 2;           // 32-wide hid block of this CTA

    float acc[2][8][4];
    #pragma unroll
    for (int i = 0; i < 2; i++)
        #pragma unroll
        for (int j = 0; j < 8; j++)
            #pragma unroll
            for (int q = 0; q < 4; q++) acc[i][j][q] = 0.f;

    auto load_stage = [&](int c, int buf) {
        const int kk = c * BK;
        const uint32_t st = sb + buf * STAGE;
        #pragma unroll
        for (int t = 0; t < 2; t++) {
            int idx = tid + t * 256;     // 0..511
            int row = idx >> 2;
            int c16 = idx & 3;
            uint32_t so = (uint32_t)(row * ROWB + c16 * 16);
            size_t ga = (size_t)(bm + row) * KTOT + kk + c16 * 8;
            size_t gb = (size_t)(bn + row) * KTOT + kk + c16 * 8;
            cp_async16(st + OFF_AHI + so, g_Ahi + ga);
            cp_async16(st + OFF_ALO + so, g_Alo + ga);
            cp_async16(st + OFF_BHI + so, g_Whi + gb);
            cp_async16(st + OFF_BLO + so, g_Wlo + gb);
        }
        CP_COMMIT();
    };

    // preload c_t tile (joins stage-0's commit group; done by first CP_WAIT)
    #pragma unroll
    for (int t = 0; t < 4; t++) {
        int idx = tid + t * 256;         // 0..1023
        int row = idx >> 3;
        int q = idx & 7;
        cp_async16(sb + CT_OFF + (uint32_t)(row * EPI_PITCH + q * 4) * 4,
                   c_t + (size_t)(bm + row) * 1024 + hid0 + q * 4);
    }
    load_stage(0, 0);

    for (int c = 0; c < NITER; c++) {
        const int buf = c & 1;
        if (c + 1 < NITER) {
            load_stage(c + 1, 1 - buf);
            CP_WAIT(1);
        } else {
            CP_WAIT(0);
        }
        __syncthreads();

        const uint32_t st = sb + buf * STAGE;
        #pragma unroll
        for (int ks = 0; ks < 2; ks++) {
            uint32_t ah[2][4], al[2][4];
            #pragma unroll
            for (int tm = 0; tm < 2; tm++) {
                uint32_t ra = (uint32_t)((wm0 + tm * 16 + (lane & 15)) * ROWB
                                         + ks * 32 + ((lane >> 4) << 4));
                ldsm_x4(ah[tm], st + OFF_AHI + ra);
                ldsm_x4(al[tm], st + OFF_ALO + ra);
            }
            #pragma unroll
            for (int tn4 = 0; tn4 < 4; tn4++) {
                uint32_t rb = (uint32_t)((wn0 + tn4 * 16 + ((lane >> 4) << 3) + (lane & 7)) * ROWB
                                         + ks * 32 + (((lane >> 3) & 1) << 4));
                uint32_t bh[4], bl[4];
                ldsm_x4(bh, st + OFF_BHI + rb);
                ldsm_x4(bl, st + OFF_BLO + rb);
                #pragma unroll
                for (int tm = 0; tm < 2; tm++) {
                    #pragma unroll
                    for (int s = 0; s < 2; s++) {
                        float* cc = acc[tm][tn4 * 2 + s];
                        mma_bf16(cc, ah[tm], &bh[2 * s]);   // hi*hi
                        mma_bf16(cc, ah[tm], &bl[2 * s]);   // hi*lo
                        mma_bf16(cc, al[tm], &bh[2 * s]);   // lo*hi
                    }
                }
            }
        }
        __syncthreads();
    }

    // ---- fused LSTM epilogue ----
    // cols n' = hid*4+gate; tq even -> (i,f), tq odd -> (g,o) of same hid.
    float* ct_s = reinterpret_cast<float*>(smem + CT_OFF);
    float* h_s  = reinterpret_cast<float*>(smem + H_OFF);
    float* c_s  = reinterpret_cast<float*>(smem + C_OFF);

    const int quad = lane >> 2;
    const int tq = lane & 3;
    const bool evenq = (tq & 1) == 0;

    #pragma unroll
    for (int tm = 0; tm < 2; tm++) {
        const int m_l = wm0 + tm * 16 + quad + (evenq ? 0 : 8);
        #pragma unroll
        for (int tn = 0; tn < 8; tn++) {
            const int col0 = bn + wn0 + tn * 8;
            const float2 bv = *reinterpret_cast<const float2*>(&g_bias[col0 + 2 * tq]);
            float c0 = acc[tm][tn][0] + bv.x;
            float c1 = acc[tm][tn][1] + bv.y;
            float c2 = acc[tm][tn][2] + bv.x;
            float c3 = acc[tm][tn][3] + bv.y;
            float p0 = __shfl_xor_sync(0xffffffffu, c0, 1);
            float p1 = __shfl_xor_sync(0xffffffffu, c1, 1);
            float p2 = __shfl_xor_sync(0xffffffffu, c2, 1);
            float p3 = __shfl_xor_sync(0xffffffffu, c3, 1);
            float gi, gf, gg, go;
            if (evenq) { gi = c0; gf = c1; gg = p0; go = p1; }
            else       { gi = p2; gf = p3; gg = c2; go = c3; }
            const int hl = (wn0 >> 2) + tn * 2 + (tq >> 1);    // hid local 0..31
            const float ctv = ct_s[m_l * EPI_PITCH + hl];
            const float si = sigmoidf_fast(gi);
            const float sf = sigmoidf_fast(gf);
            const float so = sigmoidf_fast(go);
            const float tg = tanhf_fast(gg);
            const float cn = sf * ctv + si * tg;
            const float hn = so * tanhf_fast(cn);
            h_s[m_l * EPI_PITCH + hl] = hn;
            c_s[m_l * EPI_PITCH + hl] = cn;
        }
    }
    __syncthreads();

    // coalesced stores: 128 rows x 8 float4 per tile
    #pragma unroll
    for (int t = 0; t < 4; t++) {
        int idx = tid + t * 256;
        int row = idx >> 3;
        int q = idx & 7;
        float4 hv = *reinterpret_cast<const float4*>(&h_s[row * EPI_PITCH + q * 4]);
        float4 cv = *reinterpret_cast<const float4*>(&c_s[row * EPI_PITCH + q * 4]);
        size_t o = (size_t)(bm + row) * 1024 + hid0 + q * 4;
        *reinterpret_cast<float4*>(&out[o]) = hv;
        *reinterpret_cast<float4*>(&out[4096ull * 1024 + o]) = cv;
    }
}

// ============================================================
extern "C" void kernel_launch(void* const* d_in, const int* in_sizes, int n_in,
                              void* d_out, int out_size)
{
    (void)in_sizes; (void)n_in; (void)out_size;
    const float* x  = (const float*)d_in[0];
    const float* ht = (const float*)d_in[1];
    const float* ct = (const float*)d_in[2];
    const float* wi = (const float*)d_in[3];
    const float* wh = (const float*)d_in[4];
    const float* bi = (const float*)d_in[5];
    const float* bh = (const float*)d_in[6];
    float* out = (float*)d_out;

    cudaFuncSetAttribute(lstm_gemm_mma, cudaFuncAttributeMaxDynamicSharedMemorySize, SMEM_TOTAL);

    convert_a<<<4096 * 512 / 256, 256>>>(x, ht);
    convert_w<<<dim3(2048 / 32, 4096 / 32), dim3(32, 8)>>>(wi, wh, bi, bh);
    lstm_gemm_mma<<<dim3(4096 / BN, 4096 / BM), 256, SMEM_TOTAL>>>(ct, out);
}

// round 6
// speedup vs baseline: 1.4635x; 1.1816x over previous
#include <cuda_runtime.h>
#include <cuda_bf16.h>
#include <cstdint>
#include <math.h>

// LSTM cell B=4096, I=H=1024, fused. mma.sync bf16 hi/lo split (3 MMAs).
// GEMM: 128x128x32 tile, 8 warps, 3-stage cp.async pipeline, XOR-swizzled
// smem (64B pitch), ONE syncthreads per iteration, fused LSTM epilogue.

#define BM 128
#define BN 128
#define BK 32
#define KTOT 2048
#define NITER (KTOT / BK)

// swizzled tiles: 128 rows x 64B, chunk' = chunk ^ ((row>>1)&3)
#define TILE_B 8192
#define OFF_AHI 0
#define OFF_ALO 8192
#define OFF_BHI 16384
#define OFF_BLO 24576
#define STAGE   32768
#define NSTAGE  3
#define SMEM_TOTAL (NSTAGE * STAGE)    // 98304 B -> 2 CTAs/SM

// epilogue staging overlays stage memory after mainloop
#define EPI_PITCH 36
#define H_OFF   0
#define C_OFF   (128 * EPI_PITCH * 4)      // 18432
#define CT_OFF  (2 * STAGE)                // stage 2 area (dead by then)

__device__ __nv_bfloat16 g_Ahi[4096ull * 2048], g_Alo[4096ull * 2048];
__device__ __nv_bfloat16 g_Whi[4096ull * 2048], g_Wlo[4096ull * 2048];  // [n'][k]
__device__ float g_bias[4096];                                          // permuted bi+bh

__device__ __forceinline__ uint32_t smem_u32(const void* p) {
    uint32_t a;
    asm("{ .reg .u64 t; cvta.to.shared.u64 t, %1; cvt.u32.u64 %0, t; }" : "=r"(a) : "l"(p));
    return a;
}
__device__ __forceinline__ void cp_async16(uint32_t s, const void* g) {
    asm volatile("cp.async.cg.shared.global [%0], [%1], 16;\n" :: "r"(s), "l"(g));
}
#define CP_COMMIT() asm volatile("cp.async.commit_group;\n" ::: "memory")
#define CP_WAIT(n)  asm volatile("cp.async.wait_group %0;\n" :: "n"(n) : "memory")

__device__ __forceinline__ void ldsm_x4(uint32_t* r, uint32_t addr) {
    asm volatile("ldmatrix.sync.aligned.m8n8.x4.shared.b16 {%0,%1,%2,%3}, [%4];"
                 : "=r"(r[0]), "=r"(r[1]), "=r"(r[2]), "=r"(r[3]) : "r"(addr));
}
__device__ __forceinline__ void mma_bf16(float* c, const uint32_t* a, const uint32_t* b) {
    asm volatile("mma.sync.aligned.m16n8k16.row.col.f32.bf16.bf16.f32 "
                 "{%0,%1,%2,%3}, {%4,%5,%6,%7}, {%8,%9}, {%0,%1,%2,%3};"
                 : "+f"(c[0]), "+f"(c[1]), "+f"(c[2]), "+f"(c[3])
                 : "r"(a[0]), "r"(a[1]), "r"(a[2]), "r"(a[3]), "r"(b[0]), "r"(b[1]));
}
__device__ __forceinline__ float sigmoidf_fast(float v) {
    return 1.f / (1.f + __expf(-v));
}
__device__ __forceinline__ float tanhf_fast(float v) {
    return 2.f / (1.f + __expf(-2.f * v)) - 1.f;
}

// swizzled byte offset within a tile for (row, 16B-chunk)
__device__ __forceinline__ uint32_t swz(int row, int chunk) {
    return (uint32_t)(row * 64 + ((chunk ^ ((row >> 1) & 3)) << 4));
}

// ============================================================
__global__ __launch_bounds__(256)
void convert_a(const float* __restrict__ x, const float* __restrict__ h)
{
    const int idx = blockIdx.x * 256 + threadIdx.x;   // over 4096*512 float4
    const int m = idx >> 9;
    const int kq = idx & 511;
    float4 v = (kq < 256)
        ? reinterpret_cast<const float4*>(x)[(size_t)m * 256 + kq]
        : reinterpret_cast<const float4*>(h)[(size_t)m * 256 + (kq - 256)];
    __nv_bfloat16 h0 = __float2bfloat16(v.x), h1 = __float2bfloat16(v.y);
    __nv_bfloat16 h2 = __float2bfloat16(v.z), h3 = __float2bfloat16(v.w);
    __nv_bfloat16 l0 = __float2bfloat16(v.x - __bfloat162float(h0));
    __nv_bfloat16 l1 = __float2bfloat16(v.y - __bfloat162float(h1));
    __nv_bfloat16 l2 = __float2bfloat16(v.z - __bfloat162float(h2));
    __nv_bfloat16 l3 = __float2bfloat16(v.w - __bfloat162float(h3));
    __nv_bfloat162 hp0(h0, h1), hp1(h2, h3), lp0(l0, l1), lp1(l2, l3);
    uint2 hv, lv;
    hv.x = *reinterpret_cast<uint32_t*>(&hp0); hv.y = *reinterpret_cast<uint32_t*>(&hp1);
    lv.x = *reinterpret_cast<uint32_t*>(&lp0); lv.y = *reinterpret_cast<uint32_t*>(&lp1);
    reinterpret_cast<uint2*>(g_Ahi)[idx] = hv;
    reinterpret_cast<uint2*>(g_Alo)[idx] = lv;
}

// ============================================================
__global__ __launch_bounds__(256)
void convert_w(const float* __restrict__ wi, const float* __restrict__ wh,
               const float* __restrict__ bi, const float* __restrict__ bh)
{
    __shared__ float tile[32][33];
    const int k0 = blockIdx.x * 32;
    const int n0 = blockIdx.y * 32;     // 32 consecutive n' (8 hids x 4 gates)
    const int tx = threadIdx.x, ty = threadIdx.y;   // (32, 8)

    const int g_gate = tx >> 3;
    const int hid = (n0 >> 2) + (tx & 7);
    const int n_src = g_gate * 1024 + hid;
    const int cp = ((tx & 7) << 2) | g_gate;

    #pragma unroll
    for (int j = 0; j < 4; j++) {
        int k = k0 + ty + j * 8;
        const float* w = (k < 1024) ? (wi + (size_t)k * 4096) : (wh + (size_t)(k - 1024) * 4096);
        tile[ty + j * 8][cp] = w[n_src];
    }
    if (blockIdx.x == 0 && ty == 0)
        g_bias[n0 + cp] = bi[n_src] + bh[n_src];
    __syncthreads();

    #pragma unroll
    for (int j = 0; j < 4; j++) {
        int np = n0 + ty + j * 8;
        float v = tile[tx][ty + j * 8];
        __nv_bfloat16 hi = __float2bfloat16(v);
        __nv_bfloat16 lo = __float2bfloat16(v - __bfloat162float(hi));
        g_Whi[(size_t)np * 2048 + k0 + tx] = hi;
        g_Wlo[(size_t)np * 2048 + k0 + tx] = lo;
    }
}

// ============================================================
// GEMM + fused LSTM epilogue. 3-stage pipeline, 1 sync/iter, 2 CTAs/SM.
// ============================================================
__global__ __launch_bounds__(256, 2)
void lstm_gemm_mma(const float* __restrict__ c_t, float* __restrict__ out)
{
    extern __shared__ char smem[];
    const uint32_t sb = smem_u32(smem);
    const int tid = threadIdx.x;
    const int lane = tid & 31;
    const int w = tid >> 5;
    const int wm0 = (w & 3) * 32;
    const int wn0 = (w >> 2) * 64;
    const int bm = blockIdx.y * BM;
    const int bn = blockIdx.x * BN;
    const int hid0 = bn >> 2;

    float acc[2][8][4];
    #pragma unroll
    for (int i = 0; i < 2; i++)
        #pragma unroll
        for (int j = 0; j < 8; j++)
            #pragma unroll
            for (int q = 0; q < 4; q++) acc[i][j][q] = 0.f;

    // loader mapping: 512 chunks/tile, 2 per thread per tile
    auto load_stage = [&](int c, int buf) {
        const int kk = c * BK;
        const uint32_t st = sb + buf * STAGE;
        #pragma unroll
        for (int t = 0; t < 2; t++) {
            int idx = tid + t * 256;     // 0..511
            int row = idx >> 2;
            int c16 = idx & 3;
            uint32_t so = swz(row, c16);
            size_t ga = (size_t)(bm + row) * KTOT + kk + c16 * 8;
            size_t gb = (size_t)(bn + row) * KTOT + kk + c16 * 8;
            cp_async16(st + OFF_AHI + so, g_Ahi + ga);
            cp_async16(st + OFF_ALO + so, g_Alo + ga);
            cp_async16(st + OFF_BHI + so, g_Whi + gb);
            cp_async16(st + OFF_BLO + so, g_Wlo + gb);
        }
        CP_COMMIT();
    };

    // per-thread ldsm rows (swizzle computed per access)
    const int rowA0 = wm0 + (lane & 15);            // + tm*16
    const int rowB0 = wn0 + ((lane >> 4) << 3) + (lane & 7);   // + tn4*16
    const int cA = lane >> 4;                       // 0/1 within 32B half
    const int cB = (lane >> 3) & 1;

    load_stage(0, 0);
    load_stage(1, 1);

    for (int c = 0; c < NITER; c++) {
        const int buf = c % NSTAGE;
        if (c + 1 < NITER) { CP_WAIT(1); } else { CP_WAIT(0); }
        __syncthreads();
        if (c + 2 < NITER) load_stage(c + 2, (c + 2) % NSTAGE);

        const uint32_t st = sb + buf * STAGE;
        #pragma unroll
        for (int ks = 0; ks < 2; ks++) {
            uint32_t ah[2][4], al[2][4];
            #pragma unroll
            for (int tm = 0; tm < 2; tm++) {
                int row = rowA0 + tm * 16;
                uint32_t ra = swz(row, ks * 2 + cA);
                ldsm_x4(ah[tm], st + OFF_AHI + ra);
                ldsm_x4(al[tm], st + OFF_ALO + ra);
            }
            #pragma unroll
            for (int tn4 = 0; tn4 < 4; tn4++) {
                int row = rowB0 + tn4 * 16;
                uint32_t rb = swz(row, ks * 2 + cB);
                uint32_t bh[4], bl[4];
                ldsm_x4(bh, st + OFF_BHI + rb);
                ldsm_x4(bl, st + OFF_BLO + rb);
                #pragma unroll
                for (int tm = 0; tm < 2; tm++) {
                    #pragma unroll
                    for (int s = 0; s < 2; s++) {
                        float* cc = acc[tm][tn4 * 2 + s];
                        mma_bf16(cc, ah[tm], &bh[2 * s]);   // hi*hi
                        mma_bf16(cc, ah[tm], &bl[2 * s]);   // hi*lo
                        mma_bf16(cc, al[tm], &bh[2 * s]);   // lo*hi
                    }
                }
            }
        }
        // no trailing sync: next iteration's barrier orders reuse
    }

    // ---- load c_t tile into (dead) stage-2 area ----
    #pragma unroll
    for (int t = 0; t < 4; t++) {
        int idx = tid + t * 256;         // 0..1023
        int row = idx >> 3;
        int q = idx & 7;
        cp_async16(sb + CT_OFF + (uint32_t)(row * EPI_PITCH + q * 4) * 4,
                   c_t + (size_t)(bm + row) * 1024 + hid0 + q * 4);
    }
    CP_COMMIT();
    CP_WAIT(0);
    __syncthreads();    // also: all warps done with mainloop before h/c staging

    float* ct_s = reinterpret_cast<float*>(smem + CT_OFF);
    float* h_s  = reinterpret_cast<float*>(smem + H_OFF);
    float* c_s  = reinterpret_cast<float*>(smem + C_OFF);

    const int quad = lane >> 2;
    const int tq = lane & 3;
    const bool evenq = (tq & 1) == 0;

    #pragma unroll
    for (int tm = 0; tm < 2; tm++) {
        const int m_l = wm0 + tm * 16 + quad + (evenq ? 0 : 8);
        #pragma unroll
        for (int tn = 0; tn < 8; tn++) {
            const int col0 = bn + wn0 + tn * 8;
            const float2 bv = *reinterpret_cast<const float2*>(&g_bias[col0 + 2 * tq]);
            float c0 = acc[tm][tn][0] + bv.x;
            float c1 = acc[tm][tn][1] + bv.y;
            float c2 = acc[tm][tn][2] + bv.x;
            float c3 = acc[tm][tn][3] + bv.y;
            float p0 = __shfl_xor_sync(0xffffffffu, c0, 1);
            float p1 = __shfl_xor_sync(0xffffffffu, c1, 1);
            float p2 = __shfl_xor_sync(0xffffffffu, c2, 1);
            float p3 = __shfl_xor_sync(0xffffffffu, c3, 1);
            float gi, gf, gg, go;
            if (evenq) { gi = c0; gf = c1; gg = p0; go = p1; }
            else       { gi = p2; gf = p3; gg = c2; go = c3; }
            const int hl = (wn0 >> 2) + tn * 2 + (tq >> 1);    // hid local 0..31
            const float ctv = ct_s[m_l * EPI_PITCH + hl];
            const float si = sigmoidf_fast(gi);
            const float sf = sigmoidf_fast(gf);
            const float so = sigmoidf_fast(go);
            const float tg = tanhf_fast(gg);
            const float cn = sf * ctv + si * tg;
            const float hn = so * tanhf_fast(cn);
            h_s[m_l * EPI_PITCH + hl] = hn;
            c_s[m_l * EPI_PITCH + hl] = cn;
        }
    }
    __syncthreads();

    #pragma unroll
    for (int t = 0; t < 4; t++) {
        int idx = tid + t * 256;
        int row = idx >> 3;
        int q = idx & 7;
        float4 hv = *reinterpret_cast<const float4*>(&h_s[row * EPI_PITCH + q * 4]);
        float4 cv = *reinterpret_cast<const float4*>(&c_s[row * EPI_PITCH + q * 4]);
        size_t o = (size_t)(bm + row) * 1024 + hid0 + q * 4;
        *reinterpret_cast<float4*>(&out[o]) = hv;
        *reinterpret_cast<float4*>(&out[4096ull * 1024 + o]) = cv;
    }
}

// ============================================================
extern "C" void kernel_launch(void* const* d_in, const int* in_sizes, int n_in,
                              void* d_out, int out_size)
{
    (void)in_sizes; (void)n_in; (void)out_size;
    const float* x  = (const float*)d_in[0];
    const float* ht = (const float*)d_in[1];
    const float* ct = (const float*)d_in[2];
    const float* wi = (const float*)d_in[3];
    const float* wh = (const float*)d_in[4];
    const float* bi = (const float*)d_in[5];
    const float* bh = (const float*)d_in[6];
    float* out = (float*)d_out;

    cudaFuncSetAttribute(lstm_gemm_mma, cudaFuncAttributeMaxDynamicSharedMemorySize, SMEM_TOTAL);

    convert_a<<<4096 * 512 / 256, 256>>>(x, ht);
    convert_w<<<dim3(2048 / 32, 4096 / 32), dim3(32, 8)>>>(wi, wh, bi, bh);
    lstm_gemm_mma<<<dim3(4096 / BN, 4096 / BM), 256, SMEM_TOTAL>>>(ct, out);
}